// round 8
// baseline (speedup 1.0000x reference)
#include <cuda_runtime.h>
#include <cstdint>

#define BB 16
#define SS 4096
#define SK 4097
#define DD 1024
#define HH 16
#define HD 64
#define SP 4112

typedef unsigned long long u64;

__device__ __forceinline__ void ffma2(u64& acc, u64 a, u64 b) {
    asm("fma.rn.f32x2 %0, %1, %2, %0;" : "+l"(acc) : "l"(a), "l"(b));
}
__device__ __forceinline__ float2 unpack2(u64 v) {
    float2 f; asm("mov.b64 {%0, %1}, %2;" : "=f"(f.x), "=f"(f.y) : "l"(v)); return f;
}

// ---------------- scratch ----------------
__device__ float g_q[BB * DD];   // (kept for layout stability; unused now)
__device__ float g_R[BB * HH * DD];
__device__ float g_sc[BB * HH * SP];
__device__ float g_W[BB * HH * DD];
__device__ float g_ctx[BB * DD];

// ---------------- A: fused q-proj + r-proj per (b,h); also zero g_W ---------
// grid 256 = (b,h); 256 threads.
// Phase 1: 64 q-values for this head (4 threads per 1024-dot).
// Phase 2: r[b][h][d] = sum_j Wk[h*64+j][d] * qh[j].
__global__ void k_qrproj(const float* __restrict__ query,
                         const float* __restrict__ w_in,
                         const float* __restrict__ b_in) {
    int b = blockIdx.x >> 4, h = blockIdx.x & 15;
    int t = threadIdx.x;
    __shared__ float part[256];
    __shared__ float qh[HD];
    {
        int j = t >> 2, seg = t & 3;
        const float* qr = query + b * DD + seg * 256;
        const float* wr = w_in + (size_t)(h * HD + j) * DD + seg * 256;
        float acc = 0.f;
        #pragma unroll 8
        for (int k = 0; k < 256; k += 4) {
            float4 a = *(const float4*)(qr + k);
            float4 w = *(const float4*)(wr + k);
            acc += a.x * w.x + a.y * w.y + a.z * w.z + a.w * w.w;
        }
        part[t] = acc;
    }
    *(float4*)&g_W[(b * HH + h) * DD + 4 * t] = make_float4(0.f, 0.f, 0.f, 0.f);
    __syncthreads();
    if (t < 64) {
        qh[t] = (part[4 * t] + part[4 * t + 1] + part[4 * t + 2] + part[4 * t + 3]
                 + b_in[h * HD + t]) * 0.125f;
    }
    __syncthreads();
    float4 acc = make_float4(0.f, 0.f, 0.f, 0.f);
    const float* wk = w_in + (size_t)(DD + h * HD) * DD + 4 * t;
    #pragma unroll 8
    for (int j = 0; j < HD; j++) {
        float4 w = *(const float4*)(wk + (size_t)j * DD);
        float qv = qh[j];
        acc.x += w.x * qv; acc.y += w.y * qv; acc.z += w.z * qv; acc.w += w.w * qv;
    }
    *(float4*)&g_R[(b * HH + h) * DD + 4 * t] = acc;
}

// ---------------- B: fused copy-K + scores, tiled GEMM v5 (occupancy) -------
// grid (17,16); 256 threads. 4h x 4s per thread; launch_bounds(256,3) caps
// regs at 84 -> 3 CTAs/SM; unroll 4 keeps live ranges under the cap.
__global__ void __launch_bounds__(256, 3) k_scores_copyk(
    const float* __restrict__ past_key, const float* __restrict__ key,
    float* __restrict__ comb_key) {
    const int b = blockIdx.y;
    const int s0 = blockIdx.x * 256;
    const int t = threadIdx.x;
    const int warp = t >> 5, lane = t & 31;
    const int hbase = (warp >> 1) * 4;
    const int sgrp = ((warp & 1) << 5) | lane;   // 0..63
    __shared__ float Rt[HH][34];
    __shared__ float CKt[256][34];
    u64 acc[4][4] = {};

    const int lrow = t >> 3;           // 0..31
    const int lc   = (t & 7) * 4;      // 0,4,..28

    for (int dc = 0; dc < DD; dc += 32) {
        __syncthreads();
        if (t < 128) {
            int rr = t >> 3;
            float4 v = *(const float4*)&g_R[(size_t)(b * HH + rr) * DD + dc + lc];
            *(float2*)&Rt[rr][lc]     = make_float2(v.x, v.y);
            *(float2*)&Rt[rr][lc + 2] = make_float2(v.z, v.w);
        }
        #pragma unroll 4
        for (int p = 0; p < 8; p++) {
            int row = p * 32 + lrow;
            int s = s0 + row;
            float4 v;
            if (s < SS) {
                v = *(const float4*)&past_key[((size_t)b * SS + s) * DD + dc + lc];
                *(float4*)&comb_key[((size_t)b * SK + s) * DD + dc + lc] = v;
            } else if (s == SS) {
                v = *(const float4*)&key[(size_t)b * DD + dc + lc];
                *(float4*)&comb_key[((size_t)b * SK + s) * DD + dc + lc] = v;
            } else {
                v = make_float4(0.f, 0.f, 0.f, 0.f);
            }
            *(float2*)&CKt[row][lc]     = make_float2(v.x, v.y);
            *(float2*)&CKt[row][lc + 2] = make_float2(v.z, v.w);
        }
        __syncthreads();
        #pragma unroll 4
        for (int dd = 0; dd < 32; dd += 2) {
            u64 r2[4], c2[4];
            #pragma unroll
            for (int i = 0; i < 4; i++) r2[i] = *(const u64*)&Rt[hbase + i][dd];
            #pragma unroll
            for (int j = 0; j < 4; j++) c2[j] = *(const u64*)&CKt[sgrp + 64 * j][dd];
            #pragma unroll
            for (int i = 0; i < 4; i++) {
                #pragma unroll
                for (int j = 0; j < 4; j++) ffma2(acc[i][j], r2[i], c2[j]);
            }
        }
    }
    #pragma unroll
    for (int i = 0; i < 4; i++) {
        #pragma unroll
        for (int j = 0; j < 4; j++) {
            int s = s0 + sgrp + 64 * j;
            if (s < SK) {
                float2 f = unpack2(acc[i][j]);
                g_sc[(size_t)(b * HH + hbase + i) * SP + s] = f.x + f.y;
            }
        }
    }
}

// ---------------- C: softmax, 512 threads ----------------
__global__ void k_softmax() {
    int b = blockIdx.x >> 4, h = blockIdx.x & 15;
    float* sc = g_sc + (size_t)(b * HH + h) * SP;
    __shared__ float buf[SK];
    __shared__ float red[512];
    int t = threadIdx.x;
    float m = -1e30f;
    for (int i = t; i < SK; i += 512) { float v = sc[i]; buf[i] = v; m = fmaxf(m, v); }
    red[t] = m; __syncthreads();
    for (int o = 256; o; o >>= 1) { if (t < o) red[t] = fmaxf(red[t], red[t + o]); __syncthreads(); }
    m = red[0]; __syncthreads();
    float s = 0.f;
    for (int i = t; i < SK; i += 512) { float e = __expf(buf[i] - m); buf[i] = e; s += e; }
    red[t] = s; __syncthreads();
    for (int o = 256; o; o >>= 1) { if (t < o) red[t] += red[t + o]; __syncthreads(); }
    float inv = 1.f / red[0];
    __syncthreads();
    for (int i = t; i < SK; i += 512) sc[i] = buf[i] * inv;
}

// ---------------- D: fused copy-V + weighted sum (unchanged; now profiled) --
__global__ void __launch_bounds__(256) k_wsum_copyv(
    const float* __restrict__ past_value, const float* __restrict__ value,
    float* __restrict__ comb_value) {
    int b = blockIdx.y;
    int s0 = blockIdx.x * 256;
    int t = threadIdx.x;
    __shared__ float At[HH][256];
    #pragma unroll
    for (int p = 0; p < 16; p++) {
        int idx = p * 256 + t;
        int h = idx >> 8, sl = idx & 255;
        int s = s0 + sl;
        At[h][sl] = (s < SK) ? g_sc[(size_t)(b * HH + h) * SP + s] : 0.f;
    }
    __syncthreads();
    float4 acc[HH];
    #pragma unroll
    for (int h = 0; h < HH; h++) acc[h] = make_float4(0.f, 0.f, 0.f, 0.f);
    const int d = 4 * t;
    const bool fast = (s0 + 256 <= SS);

    for (int sg = 0; sg < 256; sg += 4) {
        float4 cv[4];
        #pragma unroll
        for (int j = 0; j < 4; j++) {
            int s = s0 + sg + j;
            if (fast || s < SS) {
                cv[j] = *(const float4*)&past_value[((size_t)b * SS + s) * DD + d];
                *(float4*)&comb_value[((size_t)b * SK + s) * DD + d] = cv[j];
            } else if (s == SS) {
                cv[j] = *(const float4*)&value[b * DD + d];
                *(float4*)&comb_value[((size_t)b * SK + s) * DD + d] = cv[j];
            } else {
                cv[j] = make_float4(0.f, 0.f, 0.f, 0.f);
            }
        }
        #pragma unroll
        for (int h = 0; h < HH; h++) {
            float4 a = *(const float4*)&At[h][sg];
            acc[h].x += a.x * cv[0].x + a.y * cv[1].x + a.z * cv[2].x + a.w * cv[3].x;
            acc[h].y += a.x * cv[0].y + a.y * cv[1].y + a.z * cv[2].y + a.w * cv[3].y;
            acc[h].z += a.x * cv[0].z + a.y * cv[1].z + a.z * cv[2].z + a.w * cv[3].z;
            acc[h].w += a.x * cv[0].w + a.y * cv[1].w + a.z * cv[2].w + a.w * cv[3].w;
        }
    }
    #pragma unroll
    for (int h = 0; h < HH; h++) {
        float* w = &g_W[(size_t)(b * HH + h) * DD + d];
        atomicAdd(w + 0, acc[h].x);
        atomicAdd(w + 1, acc[h].y);
        atomicAdd(w + 2, acc[h].z);
        atomicAdd(w + 3, acc[h].w);
    }
}

// ---------------- E1: ctx ----------------
__global__ void k_ctxproj(const float* __restrict__ w_in,
                          const float* __restrict__ b_in) {
    int o = blockIdx.x * 8 + (threadIdx.x >> 5);
    int lane = threadIdx.x & 31;
    int b = o & 15, i = o >> 4, h = i >> 6;
    const float* wv = w_in + (size_t)(2 * DD + i) * DD;
    const float* Wb = g_W + (size_t)(b * HH + h) * DD;
    float acc = 0.f;
    #pragma unroll
    for (int k = lane * 4; k < DD; k += 128) {
        float4 a = *(const float4*)(wv + k);
        float4 w = *(const float4*)(Wb + k);
        acc += a.x * w.x + a.y * w.y + a.z * w.z + a.w * w.w;
    }
    #pragma unroll
    for (int off = 16; off; off >>= 1) acc += __shfl_down_sync(0xffffffffu, acc, off);
    if (lane == 0) g_ctx[b * DD + i] = acc + b_in[2 * DD + i];
}

// ---------------- E2: out ----------------
__global__ void k_outproj(const float* __restrict__ w_out,
                          const float* __restrict__ b_out,
                          float* __restrict__ out) {
    int o = blockIdx.x * 8 + (threadIdx.x >> 5);
    int lane = threadIdx.x & 31;
    int b = o & 15, i = o >> 4;
    const float* wr = w_out + (size_t)i * DD;
    const float* cx = g_ctx + b * DD;
    float acc = 0.f;
    #pragma unroll
    for (int k = lane * 4; k < DD; k += 128) {
        float4 a = *(const float4*)(wr + k);
        float4 w = *(const float4*)(cx + k);
        acc += a.x * w.x + a.y * w.y + a.z * w.z + a.w * w.w;
    }
    #pragma unroll
    for (int off = 16; off; off >>= 1) acc += __shfl_down_sync(0xffffffffu, acc, off);
    if (lane == 0) out[b * DD + i] = acc + b_out[i];
}

// ---------------- launch ----------------
extern "C" void kernel_launch(void* const* d_in, const int* in_sizes, int n_in,
                              void* d_out, int out_size) {
    const float* query      = (const float*)d_in[0];
    const float* key        = (const float*)d_in[1];
    const float* value      = (const float*)d_in[2];
    const float* past_key   = (const float*)d_in[3];
    const float* past_value = (const float*)d_in[4];
    const float* w_in       = (const float*)d_in[5];
    const float* b_in       = (const float*)d_in[6];
    const float* w_out      = (const float*)d_in[7];
    const float* b_out      = (const float*)d_in[8];

    float* out        = (float*)d_out;
    float* comb_key   = out + (size_t)BB * DD;
    float* comb_value = comb_key + (size_t)BB * SK * DD;

    k_qrproj<<<256, 256>>>(query, w_in, b_in);
    k_scores_copyk<<<dim3(17, 16), 256>>>(past_key, key, comb_key);
    k_softmax<<<256, 512>>>();
    k_wsum_copyv<<<dim3(17, 16), 256>>>(past_value, value, comb_value);
    k_ctxproj<<<2048, 256>>>(w_in, b_in);
    k_outproj<<<2048, 256>>>(w_out, b_out, out);
}